// round 9
// baseline (speedup 1.0000x reference)
#include <cuda_runtime.h>
#include <math.h>
#include <stdint.h>

#define NMAX 200000
#define NB 4
#define TOPK 1024
#define HBINS 8192
#define CAP 4096
#define THR 0.1f
#define GRID 148
#define NTHR 1024
#define FULL 0xffffffffu
#define TROWS 64                      // points per TMA tile
#define TILE_BYTES (TROWS * 1024)     // 64KB
#define DSMEM (2 * TILE_BYTES)        // 128KB dynamic staging

// ---------------- device scratch ----------------
__device__ float g_score[NMAX];
__device__ int   g_hist[NB][HBINS];            // re-zeroed in P6 each run
__device__ int   g_cnt[NB];                    // re-zeroed in P5 each run
__device__ unsigned long long g_cand[NB][CAP];
__device__ unsigned long long g_sel[NB][TOPK];
__device__ float g_nms[NB][TOPK][5];
__device__ float g_top[NB][TOPK][8];
__device__ unsigned g_mask[NB][32][TOPK];
__device__ int g_bar_count;
__device__ volatile unsigned g_bar_gen;

struct SmemU {
    union {
        unsigned long long sk[CAP];                             // 32KB  P4 rank
        float wsm[9 * 264];                                     // 9.3KB P5
        struct { float sx1[TOPK], sx2[TOPK], sy1[TOPK], sy2[TOPK], sa[TOPK]; } iou;
        struct {
            unsigned sdiag[TOPK];
            int sslot[TOPK];
            unsigned srows[256][32];
            unsigned char sflag[TOPK];
            unsigned sremv[32];
            unsigned skeepw[32];
            int scount;
        } nms;                                                  // ~41.3KB P7
    } u;
    int sthr[NB];
    unsigned long long mbar[2];
};

__device__ __forceinline__ void gridbar() {
    __syncthreads();
    if (threadIdx.x == 0) {
        __threadfence();
        unsigned gen = g_bar_gen;
        if (atomicAdd(&g_bar_count, 1) == GRID - 1) {
            g_bar_count = 0;
            __threadfence();
            g_bar_gen = gen + 1u;
        } else {
            while (g_bar_gen == gen) { __nanosleep(64); }
        }
        __threadfence();
    }
    __syncthreads();
}

__device__ __forceinline__ void mbar_wait(unsigned mbar, unsigned parity) {
    asm volatile(
        "{\n\t"
        ".reg .pred P;\n"
        "WL%=:\n\t"
        "mbarrier.try_wait.parity.acquire.cta.shared::cta.b64 P, [%0], %1, 0x989680;\n\t"
        "@!P bra WL%=;\n\t"
        "}"
        :: "r"(mbar), "r"(parity) : "memory");
}

__device__ __forceinline__ void tma_issue(const float* __restrict__ src,
                                          unsigned sdst, unsigned mbar,
                                          unsigned bytes) {
    asm volatile("mbarrier.arrive.expect_tx.shared.b64 _, [%0], %1;"
                 :: "r"(mbar), "r"(bytes) : "memory");
    asm volatile(
        "cp.async.bulk.shared::cluster.global.mbarrier::complete_tx::bytes "
        "[%0], [%1], %2, [%3];"
        :: "r"(sdst), "l"(src), "r"(bytes), "r"(mbar) : "memory");
}

// ---------------- single fused persistent kernel ----------------
__global__ __launch_bounds__(NTHR, 1) void k_all(
    const float* __restrict__ feat, const int* __restrict__ bidx,
    const int* __restrict__ coor,
    const float* __restrict__ Wc, const float* __restrict__ bc,
    const float* __restrict__ Wr, const float* __restrict__ br,
    float* __restrict__ out, int N)
{
    extern __shared__ float stg[];      // 2 x 64KB staging
    __shared__ SmemU sm;
    int tid = threadIdx.x;
    int lane = tid & 31;
    int wid = tid >> 5;

    // ================ P0: TMA-staged score GEMV (bit-exact) + fused histogram ===
    {
        unsigned mb0 = (unsigned)__cvta_generic_to_shared(&sm.mbar[0]);
        unsigned mb1 = (unsigned)__cvta_generic_to_shared(&sm.mbar[1]);
        unsigned sbase = (unsigned)__cvta_generic_to_shared(stg);
        int ntiles = (N + TROWS - 1) / TROWS;

        if (tid == 0) {
            asm volatile("mbarrier.init.shared.b64 [%0], 1;" :: "r"(mb0) : "memory");
            asm volatile("mbarrier.init.shared.b64 [%0], 1;" :: "r"(mb1) : "memory");
        }
        __syncthreads();

        float wc0[8], wc1[8], ws8[8];
#pragma unroll
        for (int k = 0; k < 8; k++) {
            int c = lane * 8 + k;
            wc0[k] = Wc[c * 2 + 0];
            wc1[k] = Wc[c * 2 + 1];
            ws8[k] = Wr[c * 9 + 8];
        }
        float bc0 = bc[0], bc1 = bc[1];
        float br8 = br[8];

        // prologue: issue tiles bid and bid+GRID
        if (tid == 0) {
            int t0 = blockIdx.x;
            if (t0 < ntiles) {
                int p0 = t0 * TROWS;
                unsigned bytes = (unsigned)(min(TROWS, N - p0) * 1024);
                tma_issue(feat + (size_t)p0 * 256, sbase, mb0, bytes);
            }
            int t1 = blockIdx.x + GRID;
            if (t1 < ntiles) {
                int p0 = t1 * TROWS;
                unsigned bytes = (unsigned)(min(TROWS, N - p0) * 1024);
                tma_issue(feat + (size_t)p0 * 256, sbase + TILE_BYTES, mb1, bytes);
            }
        }

        int it = 0;
        for (int t = blockIdx.x; t < ntiles; t += GRID, it++) {
            int buf = it & 1;
            unsigned parity = (unsigned)((it >> 1) & 1);
            mbar_wait(buf ? mb1 : mb0, parity);

            int p0 = t * TROWS;
            int rows = min(TROWS, N - p0);
            const float* sb = stg + buf * (TILE_BYTES / 4);
#pragma unroll
            for (int rr = 0; rr < 2; rr++) {
                int row = 2 * wid + rr;
                if (row < rows) {
                    int p = p0 + row;
                    const float4* fp = (const float4*)(sb + row * 256 + lane * 8);
                    float4 f0 = fp[0], f1 = fp[1];
                    float fv[8] = {f0.x, f0.y, f0.z, f0.w, f1.x, f1.y, f1.z, f1.w};
                    float a0 = 0.f, a1 = 0.f, a10 = 0.f;
#pragma unroll
                    for (int k = 0; k < 8; k++) {
                        a0 = fmaf(fv[k], wc0[k], a0);
                        a1 = fmaf(fv[k], wc1[k], a1);
                        a10 = fmaf(fv[k], ws8[k], a10);
                    }
#pragma unroll
                    for (int off = 16; off > 0; off >>= 1) {
                        a0 += __shfl_xor_sync(FULL, a0, off);
                        a1 += __shfl_xor_sync(FULL, a1, off);
                        a10 += __shfl_xor_sync(FULL, a10, off);
                    }
                    if (lane == 0) {
                        float l0 = a0 + bc0, l1 = a1 + bc1;
                        float conf = 1.f / (1.f + expf(l0 - l1));
                        float s8 = a10 + br8;
                        float scr = 1.f / (1.f + expf(-s8));
                        float score = conf * scr;
                        g_score[p] = score;
                        int b = bidx[p];
                        int bin = (int)(score * (float)HBINS);
                        bin = max(0, min(HBINS - 1, bin));
                        atomicAdd(&g_hist[b][bin], 1);
                    }
                }
            }
            __syncthreads();   // everyone done reading buf before refill
            int tn = t + 2 * GRID;
            if (tid == 0 && tn < ntiles) {
                int pn = tn * TROWS;
                unsigned bytes = (unsigned)(min(TROWS, N - pn) * 1024);
                tma_issue(feat + (size_t)pn * 256,
                          sbase + buf * TILE_BYTES, buf ? mb1 : mb0, bytes);
            }
        }
    }
    gridbar();  // BAR1

    // ================ P2: threshold (warps 0..3, redundant per block) ================
    if (wid < NB) {
        int b = wid;
        const int SEG = HBINS / 32;   // 256
        const int SUB = SEG / 32;     // 8
        int s = 0;
        {
            const int4* hp = (const int4*)&g_hist[b][lane * SEG];
#pragma unroll
            for (int i = 0; i < SEG / 4; i++) {
                int4 v = hp[i];
                s += v.x + v.y + v.z + v.w;
            }
        }
        int suf = s;
#pragma unroll
        for (int off = 1; off < 32; off <<= 1) {
            int o = __shfl_down_sync(FULL, suf, off);
            if (lane + off < 32) suf += o;
        }
        unsigned m = __ballot_sync(FULL, suf >= TOPK);
        int T = 0;
        if (m) {
            int lstar = 31 - __clz(m);
            int sufn = __shfl_down_sync(FULL, suf, 1);
            int myabove = (lane == 31) ? 0 : sufn;
            int above = __shfl_sync(FULL, myabove, lstar);
            int b0 = lstar * SEG;
            int s2 = 0;
#pragma unroll
            for (int i = 0; i < SUB; i++) s2 += g_hist[b][b0 + lane * SUB + i];
            int suf2 = s2;
#pragma unroll
            for (int off = 1; off < 32; off <<= 1) {
                int o = __shfl_down_sync(FULL, suf2, off);
                if (lane + off < 32) suf2 += o;
            }
            unsigned m2 = __ballot_sync(FULL, above + suf2 >= TOPK);
            int l2 = 31 - __clz(m2);
            int sufn2 = __shfl_down_sync(FULL, suf2, 1);
            int myabove2 = (lane == 31) ? 0 : sufn2;
            int above2 = above + __shfl_sync(FULL, myabove2, l2);
            int Tl = 0;
            if (lane == l2) {
                int acc = above2;
                for (int bin = b0 + l2 * SUB + SUB - 1; bin >= b0 + l2 * SUB; bin--) {
                    acc += g_hist[b][bin];
                    if (acc >= TOPK) { Tl = bin; break; }
                }
            }
            T = __shfl_sync(FULL, Tl, l2);
        }
        if (lane == 0) sm.sthr[b] = T;
    }
    __syncthreads();

    // ================ P3: compact (warp-aggregated) ================
    for (int p = blockIdx.x * NTHR + tid; ; p += GRID * NTHR) {
        bool live = p < N;
        if (!__ballot_sync(FULL, live)) break;
        bool pass = false;
        int b = 0;
        unsigned long long key = 0ull;
        if (live) {
            float s = g_score[p];
            b = bidx[p];
            int bin = (int)(s * (float)HBINS);
            bin = max(0, min(HBINS - 1, bin));
            pass = bin >= sm.sthr[b];
            key = ((unsigned long long)__float_as_uint(s) << 32) | (unsigned)(~(unsigned)p);
        }
#pragma unroll
        for (int bb = 0; bb < NB; bb++) {
            unsigned m = __ballot_sync(FULL, pass && b == bb);
            if (m) {
                int leader = __ffs(m) - 1;
                int base = 0;
                if (lane == leader) base = atomicAdd(&g_cnt[bb], __popc(m));
                base = __shfl_sync(FULL, base, leader);
                if (pass && b == bb) {
                    int pos = base + __popc(m & ((1u << lane) - 1u));
                    if (pos < CAP) g_cand[bb][pos] = key;
                }
            }
        }
    }
    gridbar();  // BAR2

    // ================ P4: rank-and-scatter top-K (blocks 0..127) ================
    if (blockIdx.x < 128) {
        int b = blockIdx.x >> 5, chunk = blockIdx.x & 31;
        int cnt = min(g_cnt[b], CAP);
        for (int i = tid; i < cnt; i += NTHR) sm.u.sk[i] = g_cand[b][i];
        __syncthreads();
        for (int i = chunk * 32 + wid; i < cnt; i += 1024) {
            unsigned long long key = sm.u.sk[i];
            unsigned c = 0;
            for (int j = lane; j < cnt; j += 32)
                c += (sm.u.sk[j] > key) ? 1u : 0u;
            unsigned r = __reduce_add_sync(FULL, c);
            if (r < TOPK) g_sel[b][r] = key;
        }
    }
    gridbar();  // BAR3

    // ================ P5: decode selected boxes (blocks 0..127) ================
    if (blockIdx.x < 128) {
        for (int i = tid; i < 9 * 256; i += NTHR) {
            int o = i >> 8, f = i & 255;
            sm.u.wsm[o * 264 + f + (f >> 5)] = Wr[f * 9 + o];
        }
        if (tid == 0 && blockIdx.x < NB) g_cnt[blockIdx.x] = 0;  // re-zero for replay
        __syncthreads();
        int idx = blockIdx.x * 32 + wid;     // 0..4095
        int b = idx >> 10, t = idx & (TOPK - 1);
        unsigned long long key = g_sel[b][t];
        unsigned p = ~(unsigned)(key & 0xffffffffu);
        float score = __uint_as_float((unsigned)(key >> 32));
        bool valid = (key != 0ull) && (p < (unsigned)N);
        float bx[7];
        if (valid) {
            const float4* fp = (const float4*)(feat + (size_t)p * 256 + lane * 8);
            float4 f0 = fp[0], f1 = fp[1];
            float fv[8] = {f0.x, f0.y, f0.z, f0.w, f1.x, f1.y, f1.z, f1.w};
            float acc[9];
#pragma unroll
            for (int o = 0; o < 9; o++) acc[o] = 0.f;
#pragma unroll
            for (int o = 0; o < 9; o++)
#pragma unroll
                for (int k = 0; k < 8; k++) {
                    int f = 8 * lane + k;
                    float wv = sm.u.wsm[o * 264 + f + (f >> 5)];
                    acc[o] = fmaf(fv[k], wv, acc[o]);
                }
#pragma unroll
            for (int off = 16; off > 0; off >>= 1)
#pragma unroll
                for (int o = 0; o < 9; o++)
                    acc[o] += __shfl_xor_sync(FULL, acc[o], off);
            float r0 = acc[0] + br[0], r1 = acc[1] + br[1], r2 = acc[2] + br[2];
            float d0 = acc[3] + br[3], d1 = acc[4] + br[4], d2 = acc[5] + br[5];
            float a0 = acc[6] + br[6], a1 = acc[7] + br[7];
            int cx = coor[p * 2 + 0], cy = coor[p * 2 + 1];
            bx[0] = (float)cx * 0.8f + r0;
            bx[1] = (float)cy * 0.8f + r1;
            bx[2] = r2;
            bx[3] = expf(fminf(fmaxf(d0, -6.f), 6.f));
            bx[4] = expf(fminf(fmaxf(d1, -6.f), 6.f));
            bx[5] = expf(fminf(fmaxf(d2, -6.f), 6.f));
            bx[6] = atan2f(a0, a1);
        } else {
#pragma unroll
            for (int c = 0; c < 7; c++) bx[c] = 0.f;
            score = 0.f;
        }
        if (lane == 0) {
#pragma unroll
            for (int c = 0; c < 7; c++) g_top[b][t][c] = bx[c];
            g_top[b][t][7] = score;
            float x = bx[0], y = bx[1], l = bx[3], w = bx[4];
            g_nms[b][t][0] = x - l * 0.5f;
            g_nms[b][t][1] = x + l * 0.5f;
            g_nms[b][t][2] = y - w * 0.5f;
            g_nms[b][t][3] = y + w * 0.5f;
            g_nms[b][t][4] = l * w;
        }
    }
    gridbar();  // BAR4

    // ================ P6: IoU bitmask (blocks 0..127) + re-zero g_hist ================
    if (blockIdx.x < 128) {
        int b = blockIdx.x >> 5, rg = blockIdx.x & 31;
        for (int i = tid; i < TOPK; i += NTHR) {
            sm.u.iou.sx1[i] = g_nms[b][i][0];
            sm.u.iou.sx2[i] = g_nms[b][i][1];
            sm.u.iou.sy1[i] = g_nms[b][i][2];
            sm.u.iou.sy2[i] = g_nms[b][i][3];
            sm.u.iou.sa[i]  = g_nms[b][i][4];
        }
        __syncthreads();
        int col = tid, wp = tid >> 5;
        float cx1 = sm.u.iou.sx1[col], cx2 = sm.u.iou.sx2[col];
        float cy1 = sm.u.iou.sy1[col], cy2 = sm.u.iou.sy2[col], ca = sm.u.iou.sa[col];
        for (int rr = 0; rr < 32; rr++) {
            int r = rg * 32 + rr;
            float rx1 = sm.u.iou.sx1[r], rx2 = sm.u.iou.sx2[r];
            float ry1 = sm.u.iou.sy1[r], ry2 = sm.u.iou.sy2[r], ra = sm.u.iou.sa[r];
            float ix = fmaxf(fminf(rx2, cx2) - fmaxf(rx1, cx1), 0.f);
            float iy = fmaxf(fminf(ry2, cy2) - fmaxf(ry1, cy1), 0.f);
            float inter = ix * iy;
            float uni = fmaxf(ra + ca - inter, 1e-6f);
            bool sup = inter > THR * uni;
            unsigned bal = __ballot_sync(FULL, sup);
            if (lane == 0) g_mask[b][wp][r] = bal;
        }
        if (tid < 256) ((int*)g_hist)[blockIdx.x * 256 + tid] = 0;
    }
    gridbar();  // BAR5

    // ================ P7: sequential NMS + output (blocks 0..3) ================
    if (blockIdx.x >= NB) return;
    {
        int b = blockIdx.x;
        int t = tid;
        if (t == 0) sm.u.nms.scount = 0;
        if (t < 32) sm.u.nms.sremv[t] = 0;
        __syncthreads();
        {
            int r = t;
            unsigned v[32];
#pragma unroll
            for (int w = 0; w < 32; w++) v[w] = g_mask[b][w][r];
            int wd = r >> 5;
            unsigned above = ~((2u << (r & 31)) - 1u);
            unsigned dg = v[wd] & above;
            sm.u.nms.sdiag[r] = dg;
            unsigned hi = 0;
#pragma unroll
            for (int w = 0; w < 32; w++)
                if (w > wd) hi |= v[w];
            bool flag = (dg != 0u) || (hi != 0u);
            sm.u.nms.sflag[r] = (unsigned char)flag;
            int slot = -2;
            if (flag) {
                slot = atomicAdd(&sm.u.nms.scount, 1);
                if (slot < 256) {
#pragma unroll
                    for (int w = 0; w < 32; w++) sm.u.nms.srows[slot][w] = v[w];
                } else slot = -2;
            }
            sm.u.nms.sslot[r] = slot;
        }
        __syncthreads();

        if (t < 32) {
            int ln = t;
            for (int ch = 0; ch < 32; ch++) {
                unsigned cur = sm.u.nms.sremv[ch];
                int r = ch * 32 + ln;
                unsigned mym = sm.u.nms.sdiag[r];
                unsigned intra = __reduce_or_sync(FULL, mym);
                unsigned keepbits;
                if (intra == 0u) {
                    keepbits = ~cur;
                } else {
                    unsigned supp = cur;
                    keepbits = 0u;
                    for (int q = 0; q < 32; q++) {
                        unsigned m = __shfl_sync(FULL, mym, q);
                        if (!((supp >> q) & 1u)) { keepbits |= (1u << q); supp |= m; }
                    }
                }
                if (ln == 0) sm.u.nms.skeepw[ch] = keepbits;
                bool mykeep = (keepbits >> ln) & 1u;
                unsigned todo = __ballot_sync(FULL, mykeep && sm.u.nms.sflag[r]);
                while (todo) {
                    int q = __ffs(todo) - 1;
                    todo &= todo - 1;
                    int rr = ch * 32 + q;
                    int slot = sm.u.nms.sslot[rr];
                    unsigned v = (slot >= 0) ? sm.u.nms.srows[slot][ln] : g_mask[b][ln][rr];
                    sm.u.nms.sremv[ln] |= v;
                }
                __syncwarp();
            }
        }
        __syncthreads();

        {
            int r = t;
            float kp = ((sm.u.nms.skeepw[r >> 5] >> (r & 31)) & 1u) ? 1.f : 0.f;
#pragma unroll
            for (int c = 0; c < 8; c++)
                out[((size_t)b * TOPK + r) * 8 + c] = g_top[b][r][c] * kp;
            out[(size_t)NB * TOPK * 8 + (size_t)b * TOPK + r] = 0.f;
            out[(size_t)NB * TOPK * 8 + (size_t)NB * TOPK + (size_t)b * TOPK + r] = kp;
        }
    }
}

// ---------------- launch ----------------
extern "C" void kernel_launch(void* const* d_in, const int* in_sizes, int n_in,
                              void* d_out, int out_size) {
    const float* feat = (const float*)d_in[0];
    const int*   bidx = (const int*)d_in[1];
    const int*   coor = (const int*)d_in[2];
    const float* Wc   = (const float*)d_in[3];
    const float* bc   = (const float*)d_in[4];
    const float* Wr   = (const float*)d_in[5];
    const float* br   = (const float*)d_in[6];
    float* out = (float*)d_out;
    int N = in_sizes[0] / 256;

    cudaFuncSetAttribute(k_all, cudaFuncAttributeMaxDynamicSharedMemorySize, DSMEM);
    k_all<<<GRID, NTHR, DSMEM>>>(feat, bidx, coor, Wc, bc, Wr, br, out, N);
}